// round 13
// baseline (speedup 1.0000x reference)
#include <cuda_runtime.h>
#include <cuda_bf16.h>
#include <cstdint>

// Problem constants (shapes fixed by the dataset)
#define MAXN 100000
#define MAXE 1600000
#define FIN  128
#define FHID 64
#define FOUT 32

// GEMM tiling (rows per CTA)
#define G1_ROWS 64
#define G2_ROWS 128

// ---------------- device scratch (no allocations allowed) ----------------
__device__ int   g_is64;          // 1 if edge_index is int64, 0 if int32
__device__ int   g_cnt[MAXN];     // in-degree (real edges only)
__device__ int   g_cur[MAXN];     // fill cursors
__device__ int   g_off[MAXN];     // CSR offsets (block-local exclusive scan)
__device__ int   g_bsum[128];     // per-block scan offsets (exclusive)
__device__ float g_dinv[MAXN];    // deg^{-1/2} (deg includes self loop)
__device__ int   g_src[MAXE];     // CSR: source node per (dst-sorted) edge
__device__ float g_g1[(size_t)MAXN * FHID];   // (x@W1)*dinv
__device__ float g_hact[(size_t)MAXN * FHID]; // relu layer-1 output
__device__ float g_g2[(size_t)MAXN * FOUT];   // (hact@W2)*dinv

// ---------------- small helpers ----------------
__device__ __forceinline__ unsigned long long pack_dup(float v) {
    unsigned long long r;
    asm("mov.b64 %0,{%1,%1};" : "=l"(r) : "f"(v));
    return r;
}
#define FMA2(acc, a, b) asm("fma.rn.f32x2 %0,%1,%2,%0;" : "+l"(acc) : "l"(a), "l"(b))

__device__ __forceinline__ int edge_at(const void* ei, long long idx, int is64) {
    if (is64) return (int)((const long long*)ei)[idx];
    return ((const int*)ei)[idx];
}

// ---------------- init: zero counters + detect edge dtype ----------------
// int64 little-endian values < 2^31  => every odd 32-bit word is zero.
__global__ void k_init(const int* ei32, int n) {
    int i = blockIdx.x * blockDim.x + threadIdx.x;
    if (i < n) { g_cnt[i] = 0; g_cur[i] = 0; }
    if (blockIdx.x == 0 && threadIdx.x < 32) {
        int lane = threadIdx.x;
        int nz = 0;
        #pragma unroll
        for (int q = 0; q < 8; q++) nz |= ei32[2 * (lane * 8 + q) + 1];
        unsigned m = __ballot_sync(0xffffffffu, nz != 0);
        if (lane == 0) g_is64 = (m == 0) ? 1 : 0;
    }
}

__global__ void k_count(const void* __restrict__ ei, int E, int n) {
    int e = blockIdx.x * blockDim.x + threadIdx.x;
    if (e < E) {
        int c = edge_at(ei, (long long)E + e, g_is64);   // col = dst
        if ((unsigned)c < (unsigned)n) atomicAdd(&g_cnt[c], 1);
    }
}

// Per-block exclusive scan of counts (1024/block) + dinv fused in.
__global__ void k_scan1(int n) {
    __shared__ int s[1024];
    int tid = threadIdx.x;
    int i = blockIdx.x * 1024 + tid;
    int v = (i < n) ? g_cnt[i] : 0;
    s[tid] = v; __syncthreads();
    #pragma unroll
    for (int d = 1; d < 1024; d <<= 1) {
        int t = (tid >= d) ? s[tid - d] : 0;
        __syncthreads();
        s[tid] += t;
        __syncthreads();
    }
    if (i < n) {
        g_off[i] = s[tid] - v;                 // block-local exclusive
        g_dinv[i] = rsqrtf((float)(v + 1));    // +1 = self loop
    }
    if (tid == 1023) g_bsum[blockIdx.x] = s[1023];
}

__global__ void k_scan2(int nb) {   // single block, nb <= 128
    __shared__ int s[128];
    int tid = threadIdx.x;
    int v = (tid < nb) ? g_bsum[tid] : 0;
    s[tid] = v; __syncthreads();
    #pragma unroll
    for (int d = 1; d < 128; d <<= 1) {
        int t = (tid >= d) ? s[tid - d] : 0;
        __syncthreads();
        s[tid] += t;
        __syncthreads();
    }
    if (tid < nb) g_bsum[tid] = s[tid] - v;    // exclusive block offsets
}

__global__ void k_fill(const void* __restrict__ ei, int E, int n) {
    int e = blockIdx.x * blockDim.x + threadIdx.x;
    if (e < E) {
        int is64 = g_is64;
        int r = edge_at(ei, e, is64);                    // row = src
        int c = edge_at(ei, (long long)E + e, is64);     // col = dst
        if ((unsigned)c < (unsigned)n && (unsigned)r < (unsigned)n) {
            int p = g_off[c] + g_bsum[c >> 10] + atomicAdd(&g_cur[c], 1);
            g_src[p] = r;
        }
    }
}

// ---------------- GEMM 1: g1 = (x @ W1) * dinv[row] ----------------
// 256 threads = 8 colgroups x 32 rowgroups; thread: 2 rows x 8 cols.
// W1 in smem (32KB); x via LDG (8 lanes share each address; CTA tile L1-resident).
__global__ __launch_bounds__(256) void k_gemm1(const float* __restrict__ x,
                                               const float* __restrict__ W, int n) {
    __shared__ float Ws[FIN * FHID];     // [128][64] = 32KB
    int tid = threadIdx.x;
    int row0 = blockIdx.x * G1_ROWS;

    for (int i = tid; i < FIN * FHID / 4; i += 256)
        ((float4*)Ws)[i] = ((const float4*)W)[i];
    __syncthreads();

    int cg = tid & 7;
    int rg = tid >> 3;
    int r0 = row0 + rg, r1 = r0 + 32;
    const float* xr0 = x + (size_t)min(r0, n - 1) * FIN;
    const float* xr1 = x + (size_t)min(r1, n - 1) * FIN;
    const float* w0 = Ws + cg * 4;
    const float* w1 = Ws + 32 + cg * 4;
    unsigned long long acc[2][4] = {};

    #pragma unroll 4
    for (int k = 0; k < FIN; k += 4) {
        float4 xv0 = __ldg((const float4*)(xr0 + k));
        float4 xv1 = __ldg((const float4*)(xr1 + k));
        #pragma unroll
        for (int s = 0; s < 4; s++) {
            ulonglong2 wA = *(const ulonglong2*)(w0 + (k + s) * FHID);
            ulonglong2 wB = *(const ulonglong2*)(w1 + (k + s) * FHID);
            unsigned long long d0 = pack_dup(((const float*)&xv0)[s]);
            unsigned long long d1 = pack_dup(((const float*)&xv1)[s]);
            FMA2(acc[0][0], d0, wA.x); FMA2(acc[0][1], d0, wA.y);
            FMA2(acc[0][2], d0, wB.x); FMA2(acc[0][3], d0, wB.y);
            FMA2(acc[1][0], d1, wA.x); FMA2(acc[1][1], d1, wA.y);
            FMA2(acc[1][2], d1, wB.x); FMA2(acc[1][3], d1, wB.y);
        }
    }
    #pragma unroll
    for (int i = 0; i < 2; i++) {
        int gr = row0 + rg + 32 * i;
        if (gr < n) {
            float dv = g_dinv[gr];
            float o[8];
            asm("mov.b64 {%0,%1},%2;" : "=f"(o[0]), "=f"(o[1]) : "l"(acc[i][0]));
            asm("mov.b64 {%0,%1},%2;" : "=f"(o[2]), "=f"(o[3]) : "l"(acc[i][1]));
            asm("mov.b64 {%0,%1},%2;" : "=f"(o[4]), "=f"(o[5]) : "l"(acc[i][2]));
            asm("mov.b64 {%0,%1},%2;" : "=f"(o[6]), "=f"(o[7]) : "l"(acc[i][3]));
            float* gp = g_g1 + (size_t)gr * FHID;
            *(float4*)(gp + cg * 4)      = make_float4(o[0]*dv, o[1]*dv, o[2]*dv, o[3]*dv);
            *(float4*)(gp + 32 + cg * 4) = make_float4(o[4]*dv, o[5]*dv, o[6]*dv, o[7]*dv);
        }
    }
}

// ---------------- GEMM 2: g2 = (hact @ W2) * dinv[row] ----------------
// 256 threads = 4 colgroups x 64 rowgroups; thread: 2 rows x 8 cols.
__global__ __launch_bounds__(256) void k_gemm2(const float* __restrict__ W, int n) {
    __shared__ float Ws[FHID * FOUT];    // [64][32] = 8KB
    int tid = threadIdx.x;
    int row0 = blockIdx.x * G2_ROWS;

    for (int i = tid; i < FHID * FOUT / 4; i += 256)
        ((float4*)Ws)[i] = ((const float4*)W)[i];
    __syncthreads();

    int cg = tid & 3;
    int rg = tid >> 2;
    int r0 = row0 + rg, r1 = r0 + 64;
    const float* xr0 = g_hact + (size_t)min(r0, n - 1) * FHID;
    const float* xr1 = g_hact + (size_t)min(r1, n - 1) * FHID;
    const float* w0 = Ws + cg * 4;
    const float* w1 = Ws + 16 + cg * 4;
    unsigned long long acc[2][4] = {};

    #pragma unroll 4
    for (int k = 0; k < FHID; k += 4) {
        float4 xv0 = __ldg((const float4*)(xr0 + k));
        float4 xv1 = __ldg((const float4*)(xr1 + k));
        #pragma unroll
        for (int s = 0; s < 4; s++) {
            ulonglong2 wA = *(const ulonglong2*)(w0 + (k + s) * FOUT);
            ulonglong2 wB = *(const ulonglong2*)(w1 + (k + s) * FOUT);
            unsigned long long d0 = pack_dup(((const float*)&xv0)[s]);
            unsigned long long d1 = pack_dup(((const float*)&xv1)[s]);
            FMA2(acc[0][0], d0, wA.x); FMA2(acc[0][1], d0, wA.y);
            FMA2(acc[0][2], d0, wB.x); FMA2(acc[0][3], d0, wB.y);
            FMA2(acc[1][0], d1, wA.x); FMA2(acc[1][1], d1, wA.y);
            FMA2(acc[1][2], d1, wB.x); FMA2(acc[1][3], d1, wB.y);
        }
    }
    #pragma unroll
    for (int i = 0; i < 2; i++) {
        int gr = row0 + rg + 64 * i;
        if (gr < n) {
            float dv = g_dinv[gr];
            float o[8];
            asm("mov.b64 {%0,%1},%2;" : "=f"(o[0]), "=f"(o[1]) : "l"(acc[i][0]));
            asm("mov.b64 {%0,%1},%2;" : "=f"(o[2]), "=f"(o[3]) : "l"(acc[i][1]));
            asm("mov.b64 {%0,%1},%2;" : "=f"(o[4]), "=f"(o[5]) : "l"(acc[i][2]));
            asm("mov.b64 {%0,%1},%2;" : "=f"(o[6]), "=f"(o[7]) : "l"(acc[i][3]));
            float* gp = g_g2 + (size_t)gr * FOUT;
            *(float4*)(gp + cg * 4)      = make_float4(o[0]*dv, o[1]*dv, o[2]*dv, o[3]*dv);
            *(float4*)(gp + 16 + cg * 4) = make_float4(o[4]*dv, o[5]*dv, o[6]*dv, o[7]*dv);
        }
    }
}

// ---------------- Gather aggregation: one warp per node, MLP=4 ----------------
// h_act[v] = relu( dinv[v] * (sum_{u->v} g1[u] + g1[v]) + b1 )
__global__ void k_gather1(const float* __restrict__ bias, int n) {
    int t = blockIdx.x * blockDim.x + threadIdx.x;
    int v = t >> 5;
    int lane = t & 31;
    if (v >= n) return;
    int base = g_off[v] + g_bsum[v >> 10];
    int c = g_cnt[v];

    float2 acc = *(const float2*)(g_g1 + (size_t)v * FHID + lane * 2);  // self loop
    int j = 0;
    for (; j + 4 <= c; j += 4) {
        int u0 = __ldg(&g_src[base + j + 0]);
        int u1 = __ldg(&g_src[base + j + 1]);
        int u2 = __ldg(&g_src[base + j + 2]);
        int u3 = __ldg(&g_src[base + j + 3]);
        float2 t0 = __ldg((const float2*)(g_g1 + (size_t)u0 * FHID) + lane);
        float2 t1 = __ldg((const float2*)(g_g1 + (size_t)u1 * FHID) + lane);
        float2 t2 = __ldg((const float2*)(g_g1 + (size_t)u2 * FHID) + lane);
        float2 t3 = __ldg((const float2*)(g_g1 + (size_t)u3 * FHID) + lane);
        acc.x += t0.x + t1.x + t2.x + t3.x;
        acc.y += t0.y + t1.y + t2.y + t3.y;
    }
    for (; j < c; j++) {
        int u = __ldg(&g_src[base + j]);
        float2 tt = __ldg((const float2*)(g_g1 + (size_t)u * FHID) + lane);
        acc.x += tt.x; acc.y += tt.y;
    }
    float dv = g_dinv[v];
    float o0 = fmaf(dv, acc.x, bias[lane * 2]);
    float o1 = fmaf(dv, acc.y, bias[lane * 2 + 1]);
    o0 = fmaxf(o0, 0.f); o1 = fmaxf(o1, 0.f);
    *(float2*)(g_hact + (size_t)v * FHID + lane * 2) = make_float2(o0, o1);
}

// out[v] = dinv[v] * (sum_{u->v} g2[u] + g2[v]) + b2
__global__ void k_gather2(const float* __restrict__ bias, float* __restrict__ outp, int n) {
    int t = blockIdx.x * blockDim.x + threadIdx.x;
    int v = t >> 5;
    int lane = t & 31;
    if (v >= n) return;
    int base = g_off[v] + g_bsum[v >> 10];
    int c = g_cnt[v];

    float acc = g_g2[(size_t)v * FOUT + lane];  // self loop
    int j = 0;
    for (; j + 4 <= c; j += 4) {
        int u0 = __ldg(&g_src[base + j + 0]);
        int u1 = __ldg(&g_src[base + j + 1]);
        int u2 = __ldg(&g_src[base + j + 2]);
        int u3 = __ldg(&g_src[base + j + 3]);
        float t0 = __ldg(g_g2 + (size_t)u0 * FOUT + lane);
        float t1 = __ldg(g_g2 + (size_t)u1 * FOUT + lane);
        float t2 = __ldg(g_g2 + (size_t)u2 * FOUT + lane);
        float t3 = __ldg(g_g2 + (size_t)u3 * FOUT + lane);
        acc += t0 + t1 + t2 + t3;
    }
    for (; j < c; j++) {
        int u = __ldg(&g_src[base + j]);
        acc += __ldg(g_g2 + (size_t)u * FOUT + lane);
    }
    float dv = g_dinv[v];
    outp[(size_t)v * FOUT + lane] = fmaf(dv, acc, bias[lane]);
}

// ---------------- launch ----------------
extern "C" void kernel_launch(void* const* d_in, const int* in_sizes, int n_in,
                              void* d_out, int out_size) {
    const float* x   = (const float*)d_in[0];
    const void*  ei  = d_in[1];                 // int32 or int64, detected on device
    const float* W1  = (const float*)d_in[2];
    const float* b1  = (const float*)d_in[3];
    const float* W2  = (const float*)d_in[4];
    const float* b2  = (const float*)d_in[5];
    float*       out = (float*)d_out;

    int n = in_sizes[0] / FIN;     // 100000
    int E = in_sizes[1] / 2;       // 1600000 (element count is dtype-independent)

    int nb = (n + 1023) / 1024;

    k_init <<<(n + 255) / 256, 256>>>((const int*)ei, n);
    k_count<<<(E + 255) / 256, 256>>>(ei, E, n);
    k_scan1<<<nb, 1024>>>(n);                                   // off + dinv + bsum
    k_gemm1<<<(n + G1_ROWS - 1) / G1_ROWS, 256>>>(x, W1, n);    // 4th launch: ncu window
    k_scan2<<<1, 128>>>(nb);
    k_fill <<<(E + 255) / 256, 256>>>(ei, E, n);
    k_gather1<<<(int)(((size_t)n * 32 + 255) / 256), 256>>>(b1, n);
    k_gemm2<<<(n + G2_ROWS - 1) / G2_ROWS, 256>>>(W2, n);
    k_gather2<<<(int)(((size_t)n * 32 + 255) / 256), 256>>>(b2, out, n);
}

// round 14
// speedup vs baseline: 1.1538x; 1.1538x over previous
#include <cuda_runtime.h>
#include <cuda_bf16.h>
#include <cuda_fp16.h>
#include <cstdint>

// Problem constants (shapes fixed by the dataset)
#define MAXN 100000
#define MAXE 1600000
#define FIN  128
#define FHID 64
#define FOUT 32

// GEMM tiling (rows per CTA)
#define G1_ROWS 96
#define G2_ROWS 256

// ---------------- device scratch (no allocations allowed) ----------------
__device__ int    g_is64;          // 1 if edge_index is int64, 0 if int32
__device__ int    g_cnt[MAXN];     // in-degree (real edges only)
__device__ int    g_cur[MAXN];     // fill cursors
__device__ int    g_off[MAXN];     // CSR offsets (block-local exclusive scan)
__device__ int    g_bsum[128];     // per-block scan offsets (exclusive)
__device__ float  g_dinv[MAXN];    // deg^{-1/2} (deg includes self loop)
__device__ int    g_src[MAXE];     // CSR: source node per (dst-sorted) edge
__device__ __half g_g1h[(size_t)MAXN * FHID];  // (x@W1)*dinv, fp16
__device__ float  g_hact[(size_t)MAXN * FHID]; // relu layer-1 output (fp32)
__device__ __half g_g2h[(size_t)MAXN * FOUT];  // (hact@W2)*dinv, fp16

// ---------------- small helpers ----------------
__device__ __forceinline__ unsigned long long pack_dup(float v) {
    unsigned long long r;
    asm("mov.b64 %0,{%1,%1};" : "=l"(r) : "f"(v));
    return r;
}
#define FMA2(acc, a, b) asm("fma.rn.f32x2 %0,%1,%2,%0;" : "+l"(acc) : "l"(a), "l"(b))

__device__ __forceinline__ unsigned h2u(__half2 h) {
    unsigned u; __builtin_memcpy(&u, &h, 4); return u;
}

__device__ __forceinline__ int edge_at(const void* ei, long long idx, int is64) {
    if (is64) return (int)((const long long*)ei)[idx];
    return ((const int*)ei)[idx];
}

// ---------------- init: zero counters + detect edge dtype ----------------
// int64 little-endian values < 2^31  => every odd 32-bit word is zero.
__global__ void k_init(const int* ei32, int n) {
    int i = blockIdx.x * blockDim.x + threadIdx.x;
    if (i < n) { g_cnt[i] = 0; g_cur[i] = 0; }
    if (blockIdx.x == 0 && threadIdx.x < 32) {
        int lane = threadIdx.x;
        int nz = 0;
        #pragma unroll
        for (int q = 0; q < 8; q++) nz |= ei32[2 * (lane * 8 + q) + 1];
        unsigned m = __ballot_sync(0xffffffffu, nz != 0);
        if (lane == 0) g_is64 = (m == 0) ? 1 : 0;
    }
}

__global__ void k_count(const void* __restrict__ ei, int E, int n) {
    int e = blockIdx.x * blockDim.x + threadIdx.x;
    if (e < E) {
        int c = edge_at(ei, (long long)E + e, g_is64);   // col = dst
        if ((unsigned)c < (unsigned)n) atomicAdd(&g_cnt[c], 1);
    }
}

// Per-block exclusive scan of counts (1024/block) + dinv fused in.
__global__ void k_scan1(int n) {
    __shared__ int s[1024];
    int tid = threadIdx.x;
    int i = blockIdx.x * 1024 + tid;
    int v = (i < n) ? g_cnt[i] : 0;
    s[tid] = v; __syncthreads();
    #pragma unroll
    for (int d = 1; d < 1024; d <<= 1) {
        int t = (tid >= d) ? s[tid - d] : 0;
        __syncthreads();
        s[tid] += t;
        __syncthreads();
    }
    if (i < n) {
        g_off[i] = s[tid] - v;                 // block-local exclusive
        g_dinv[i] = rsqrtf((float)(v + 1));    // +1 = self loop
    }
    if (tid == 1023) g_bsum[blockIdx.x] = s[1023];
}

__global__ void k_scan2(int nb) {   // single block, nb <= 128
    __shared__ int s[128];
    int tid = threadIdx.x;
    int v = (tid < nb) ? g_bsum[tid] : 0;
    s[tid] = v; __syncthreads();
    #pragma unroll
    for (int d = 1; d < 128; d <<= 1) {
        int t = (tid >= d) ? s[tid - d] : 0;
        __syncthreads();
        s[tid] += t;
        __syncthreads();
    }
    if (tid < nb) g_bsum[tid] = s[tid] - v;    // exclusive block offsets
}

__global__ void k_fill(const void* __restrict__ ei, int E, int n) {
    int e = blockIdx.x * blockDim.x + threadIdx.x;
    if (e < E) {
        int is64 = g_is64;
        int r = edge_at(ei, e, is64);                    // row = src
        int c = edge_at(ei, (long long)E + e, is64);     // col = dst
        if ((unsigned)c < (unsigned)n && (unsigned)r < (unsigned)n) {
            int p = g_off[c] + g_bsum[c >> 10] + atomicAdd(&g_cur[c], 1);
            g_src[p] = r;
        }
    }
}

// ---------------- GEMM 1: g1 = fp16( (x @ W1) * dinv[row] ) ----------------
// 256 threads = 8 colgroups x 32 rowgroups; thread: 3 rows x 8 cols.
// W1 in smem (32KB); x via LDG (8 lanes share each address; CTA tile L1-resident).
// launch_bounds(256,3): cap regs so 3 CTAs/SM fit (24 warps).
__global__ __launch_bounds__(256, 3) void k_gemm1(const float* __restrict__ x,
                                                  const float* __restrict__ W, int n) {
    __shared__ float Ws[FIN * FHID];     // [128][64] = 32KB
    int tid = threadIdx.x;
    int row0 = blockIdx.x * G1_ROWS;

    for (int i = tid; i < FIN * FHID / 4; i += 256)
        ((float4*)Ws)[i] = ((const float4*)W)[i];
    __syncthreads();

    int cg = tid & 7;
    int rg = tid >> 3;
    int r0 = row0 + rg, r1 = r0 + 32, r2 = r0 + 64;
    const float* xr0 = x + (size_t)min(r0, n - 1) * FIN;
    const float* xr1 = x + (size_t)min(r1, n - 1) * FIN;
    const float* xr2 = x + (size_t)min(r2, n - 1) * FIN;
    const float* w0 = Ws + cg * 4;
    const float* w1 = Ws + 32 + cg * 4;
    unsigned long long acc[3][4] = {};

    #pragma unroll 4
    for (int k = 0; k < FIN; k += 4) {
        float4 xv0 = __ldg((const float4*)(xr0 + k));
        float4 xv1 = __ldg((const float4*)(xr1 + k));
        float4 xv2 = __ldg((const float4*)(xr2 + k));
        #pragma unroll
        for (int s = 0; s < 4; s++) {
            ulonglong2 wA = *(const ulonglong2*)(w0 + (k + s) * FHID);
            ulonglong2 wB = *(const ulonglong2*)(w1 + (k + s) * FHID);
            unsigned long long d0 = pack_dup(((const float*)&xv0)[s]);
            unsigned long long d1 = pack_dup(((const float*)&xv1)[s]);
            unsigned long long d2 = pack_dup(((const float*)&xv2)[s]);
            FMA2(acc[0][0], d0, wA.x); FMA2(acc[0][1], d0, wA.y);
            FMA2(acc[0][2], d0, wB.x); FMA2(acc[0][3], d0, wB.y);
            FMA2(acc[1][0], d1, wA.x); FMA2(acc[1][1], d1, wA.y);
            FMA2(acc[1][2], d1, wB.x); FMA2(acc[1][3], d1, wB.y);
            FMA2(acc[2][0], d2, wA.x); FMA2(acc[2][1], d2, wA.y);
            FMA2(acc[2][2], d2, wB.x); FMA2(acc[2][3], d2, wB.y);
        }
    }
    #pragma unroll
    for (int i = 0; i < 3; i++) {
        int gr = row0 + rg + 32 * i;
        if (gr < n) {
            float dv = g_dinv[gr];
            float o[8];
            asm("mov.b64 {%0,%1},%2;" : "=f"(o[0]), "=f"(o[1]) : "l"(acc[i][0]));
            asm("mov.b64 {%0,%1},%2;" : "=f"(o[2]), "=f"(o[3]) : "l"(acc[i][1]));
            asm("mov.b64 {%0,%1},%2;" : "=f"(o[4]), "=f"(o[5]) : "l"(acc[i][2]));
            asm("mov.b64 {%0,%1},%2;" : "=f"(o[6]), "=f"(o[7]) : "l"(acc[i][3]));
            __half2 h0 = __floats2half2_rn(o[0] * dv, o[1] * dv);
            __half2 h1 = __floats2half2_rn(o[2] * dv, o[3] * dv);
            __half2 h2 = __floats2half2_rn(o[4] * dv, o[5] * dv);
            __half2 h3 = __floats2half2_rn(o[6] * dv, o[7] * dv);
            __half* gp = g_g1h + (size_t)gr * FHID;
            *(uint2*)(gp + cg * 4)      = make_uint2(h2u(h0), h2u(h1));
            *(uint2*)(gp + 32 + cg * 4) = make_uint2(h2u(h2), h2u(h3));
        }
    }
}

// ---------------- GEMM 2: g2 = fp16( (hact @ W2) * dinv[row] ) ----------------
// 256 threads = 4 colgroups x 64 rowgroups; thread: 4 rows x 8 cols.
__global__ __launch_bounds__(256) void k_gemm2(const float* __restrict__ W, int n) {
    __shared__ float Ws[FHID * FOUT];    // [64][32] = 8KB
    int tid = threadIdx.x;
    int row0 = blockIdx.x * G2_ROWS;

    for (int i = tid; i < FHID * FOUT / 4; i += 256)
        ((float4*)Ws)[i] = ((const float4*)W)[i];
    __syncthreads();

    int cg = tid & 3;
    int rg = tid >> 2;
    int r0 = row0 + rg, r1 = r0 + 64, r2 = r0 + 128, r3 = r0 + 192;
    const float* xr0 = g_hact + (size_t)min(r0, n - 1) * FHID;
    const float* xr1 = g_hact + (size_t)min(r1, n - 1) * FHID;
    const float* xr2 = g_hact + (size_t)min(r2, n - 1) * FHID;
    const float* xr3 = g_hact + (size_t)min(r3, n - 1) * FHID;
    const float* w0 = Ws + cg * 4;
    const float* w1 = Ws + 16 + cg * 4;
    unsigned long long acc[4][4] = {};

    #pragma unroll 4
    for (int k = 0; k < FHID; k += 4) {
        float4 xv0 = __ldg((const float4*)(xr0 + k));
        float4 xv1 = __ldg((const float4*)(xr1 + k));
        float4 xv2 = __ldg((const float4*)(xr2 + k));
        float4 xv3 = __ldg((const float4*)(xr3 + k));
        #pragma unroll
        for (int s = 0; s < 4; s++) {
            ulonglong2 wA = *(const ulonglong2*)(w0 + (k + s) * FOUT);
            ulonglong2 wB = *(const ulonglong2*)(w1 + (k + s) * FOUT);
            unsigned long long d0 = pack_dup(((const float*)&xv0)[s]);
            unsigned long long d1 = pack_dup(((const float*)&xv1)[s]);
            unsigned long long d2 = pack_dup(((const float*)&xv2)[s]);
            unsigned long long d3 = pack_dup(((const float*)&xv3)[s]);
            FMA2(acc[0][0], d0, wA.x); FMA2(acc[0][1], d0, wA.y);
            FMA2(acc[0][2], d0, wB.x); FMA2(acc[0][3], d0, wB.y);
            FMA2(acc[1][0], d1, wA.x); FMA2(acc[1][1], d1, wA.y);
            FMA2(acc[1][2], d1, wB.x); FMA2(acc[1][3], d1, wB.y);
            FMA2(acc[2][0], d2, wA.x); FMA2(acc[2][1], d2, wA.y);
            FMA2(acc[2][2], d2, wB.x); FMA2(acc[2][3], d2, wB.y);
            FMA2(acc[3][0], d3, wA.x); FMA2(acc[3][1], d3, wA.y);
            FMA2(acc[3][2], d3, wB.x); FMA2(acc[3][3], d3, wB.y);
        }
    }
    #pragma unroll
    for (int i = 0; i < 4; i++) {
        int gr = row0 + rg + 64 * i;
        if (gr < n) {
            float dv = g_dinv[gr];
            float o[8];
            asm("mov.b64 {%0,%1},%2;" : "=f"(o[0]), "=f"(o[1]) : "l"(acc[i][0]));
            asm("mov.b64 {%0,%1},%2;" : "=f"(o[2]), "=f"(o[3]) : "l"(acc[i][1]));
            asm("mov.b64 {%0,%1},%2;" : "=f"(o[4]), "=f"(o[5]) : "l"(acc[i][2]));
            asm("mov.b64 {%0,%1},%2;" : "=f"(o[6]), "=f"(o[7]) : "l"(acc[i][3]));
            __half2 h0 = __floats2half2_rn(o[0] * dv, o[1] * dv);
            __half2 h1 = __floats2half2_rn(o[2] * dv, o[3] * dv);
            __half2 h2 = __floats2half2_rn(o[4] * dv, o[5] * dv);
            __half2 h3 = __floats2half2_rn(o[6] * dv, o[7] * dv);
            __half* gp = g_g2h + (size_t)gr * FOUT;
            *(uint2*)(gp + cg * 4)      = make_uint2(h2u(h0), h2u(h1));
            *(uint2*)(gp + 16 + cg * 4) = make_uint2(h2u(h2), h2u(h3));
        }
    }
}

// ---------------- Gather aggregation: one warp per node, MLP=4, fp16 operands ---
// h_act[v] = relu( dinv[v] * (sum_{u->v} g1[u] + g1[v]) + b1 )
__global__ void k_gather1(const float* __restrict__ bias, int n) {
    int t = blockIdx.x * blockDim.x + threadIdx.x;
    int v = t >> 5;
    int lane = t & 31;
    if (v >= n) return;
    int base = g_off[v] + g_bsum[v >> 10];
    int c = g_cnt[v];
    const __half2* g1 = (const __half2*)g_g1h;   // row stride = 32 half2

    float2 acc = __half22float2(__ldg(g1 + (size_t)v * 32 + lane));  // self loop
    int j = 0;
    for (; j + 4 <= c; j += 4) {
        int u0 = __ldg(&g_src[base + j + 0]);
        int u1 = __ldg(&g_src[base + j + 1]);
        int u2 = __ldg(&g_src[base + j + 2]);
        int u3 = __ldg(&g_src[base + j + 3]);
        float2 t0 = __half22float2(__ldg(g1 + (size_t)u0 * 32 + lane));
        float2 t1 = __half22float2(__ldg(g1 + (size_t)u1 * 32 + lane));
        float2 t2 = __half22float2(__ldg(g1 + (size_t)u2 * 32 + lane));
        float2 t3 = __half22float2(__ldg(g1 + (size_t)u3 * 32 + lane));
        acc.x += t0.x + t1.x + t2.x + t3.x;
        acc.y += t0.y + t1.y + t2.y + t3.y;
    }
    for (; j < c; j++) {
        int u = __ldg(&g_src[base + j]);
        float2 tt = __half22float2(__ldg(g1 + (size_t)u * 32 + lane));
        acc.x += tt.x; acc.y += tt.y;
    }
    float dv = g_dinv[v];
    float o0 = fmaf(dv, acc.x, bias[lane * 2]);
    float o1 = fmaf(dv, acc.y, bias[lane * 2 + 1]);
    o0 = fmaxf(o0, 0.f); o1 = fmaxf(o1, 0.f);
    *(float2*)(g_hact + (size_t)v * FHID + lane * 2) = make_float2(o0, o1);
}

// out[v] = dinv[v] * (sum_{u->v} g2[u] + g2[v]) + b2
__global__ void k_gather2(const float* __restrict__ bias, float* __restrict__ outp, int n) {
    int t = blockIdx.x * blockDim.x + threadIdx.x;
    int v = t >> 5;
    int lane = t & 31;
    if (v >= n) return;
    int base = g_off[v] + g_bsum[v >> 10];
    int c = g_cnt[v];

    float acc = __half2float(__ldg(g_g2h + (size_t)v * FOUT + lane));  // self loop
    int j = 0;
    for (; j + 4 <= c; j += 4) {
        int u0 = __ldg(&g_src[base + j + 0]);
        int u1 = __ldg(&g_src[base + j + 1]);
        int u2 = __ldg(&g_src[base + j + 2]);
        int u3 = __ldg(&g_src[base + j + 3]);
        float t0 = __half2float(__ldg(g_g2h + (size_t)u0 * FOUT + lane));
        float t1 = __half2float(__ldg(g_g2h + (size_t)u1 * FOUT + lane));
        float t2 = __half2float(__ldg(g_g2h + (size_t)u2 * FOUT + lane));
        float t3 = __half2float(__ldg(g_g2h + (size_t)u3 * FOUT + lane));
        acc += t0 + t1 + t2 + t3;
    }
    for (; j < c; j++) {
        int u = __ldg(&g_src[base + j]);
        acc += __half2float(__ldg(g_g2h + (size_t)u * FOUT + lane));
    }
    float dv = g_dinv[v];
    outp[(size_t)v * FOUT + lane] = fmaf(dv, acc, bias[lane]);
}

// ---------------- launch ----------------
extern "C" void kernel_launch(void* const* d_in, const int* in_sizes, int n_in,
                              void* d_out, int out_size) {
    const float* x   = (const float*)d_in[0];
    const void*  ei  = d_in[1];                 // int32 or int64, detected on device
    const float* W1  = (const float*)d_in[2];
    const float* b1  = (const float*)d_in[3];
    const float* W2  = (const float*)d_in[4];
    const float* b2  = (const float*)d_in[5];
    float*       out = (float*)d_out;

    int n = in_sizes[0] / FIN;     // 100000
    int E = in_sizes[1] / 2;       // 1600000 (element count is dtype-independent)

    int nb = (n + 1023) / 1024;

    k_init <<<(n + 255) / 256, 256>>>((const int*)ei, n);
    k_count<<<(E + 255) / 256, 256>>>(ei, E, n);
    k_scan1<<<nb, 1024>>>(n);                                   // off + dinv + bsum
    k_gemm1<<<(n + G1_ROWS - 1) / G1_ROWS, 256>>>(x, W1, n);    // 4th launch: ncu window
    k_scan2<<<1, 128>>>(nb);
    k_fill <<<(E + 255) / 256, 256>>>(ei, E, n);
    k_gather1<<<(int)(((size_t)n * 32 + 255) / 256), 256>>>(b1, n);
    k_gemm2<<<(n + G2_ROWS - 1) / G2_ROWS, 256>>>(W2, n);
    k_gather2<<<(int)(((size_t)n * 32 + 255) / 256), 256>>>(b2, out, n);
}

// round 15
// speedup vs baseline: 1.3751x; 1.1918x over previous
#include <cuda_runtime.h>
#include <cuda_bf16.h>
#include <cuda_fp16.h>
#include <cstdint>

// Problem constants (shapes fixed by the dataset)
#define MAXN 100000
#define MAXE 1600000
#define FIN  128
#define FHID 64
#define FOUT 32

// GEMM tiling (rows per CTA)
#define G1_ROWS 128            // 8 warps x 16 rows (mma m16n8k16)
#define G2_ROWS 256

// ---------------- device scratch (no allocations allowed) ----------------
__device__ int    g_is64;          // 1 if edge_index is int64, 0 if int32
__device__ int    g_cnt[MAXN];     // in-degree (real edges only)
__device__ int    g_cur[MAXN];     // fill cursors
__device__ int    g_off[MAXN];     // CSR offsets (block-local exclusive scan)
__device__ int    g_bsum[128];     // per-block scan offsets (exclusive)
__device__ float  g_dinv[MAXN];    // deg^{-1/2} (deg includes self loop)
__device__ int    g_src[MAXE];     // CSR: source node per (dst-sorted) edge
__device__ __half g_g1h[(size_t)MAXN * FHID];  // (x@W1)*dinv, fp16
__device__ float  g_hact[(size_t)MAXN * FHID]; // relu layer-1 output (fp32)
__device__ __half g_g2h[(size_t)MAXN * FOUT];  // (hact@W2)*dinv, fp16

// ---------------- small helpers ----------------
__device__ __forceinline__ unsigned long long pack_dup(float v) {
    unsigned long long r;
    asm("mov.b64 %0,{%1,%1};" : "=l"(r) : "f"(v));
    return r;
}
#define FMA2(acc, a, b) asm("fma.rn.f32x2 %0,%1,%2,%0;" : "+l"(acc) : "l"(a), "l"(b))

__device__ __forceinline__ unsigned h2u(__half2 h) {
    unsigned u; __builtin_memcpy(&u, &h, 4); return u;
}

__device__ __forceinline__ int edge_at(const void* ei, long long idx, int is64) {
    if (is64) return (int)((const long long*)ei)[idx];
    return ((const int*)ei)[idx];
}

// ---------------- init: zero counters + detect edge dtype ----------------
// int64 little-endian values < 2^31  => every odd 32-bit word is zero.
__global__ void k_init(const int* ei32, int n) {
    int i = blockIdx.x * blockDim.x + threadIdx.x;
    if (i < n) { g_cnt[i] = 0; g_cur[i] = 0; }
    if (blockIdx.x == 0 && threadIdx.x < 32) {
        int lane = threadIdx.x;
        int nz = 0;
        #pragma unroll
        for (int q = 0; q < 8; q++) nz |= ei32[2 * (lane * 8 + q) + 1];
        unsigned m = __ballot_sync(0xffffffffu, nz != 0);
        if (lane == 0) g_is64 = (m == 0) ? 1 : 0;
    }
}

__global__ void k_count(const void* __restrict__ ei, int E, int n) {
    int e = blockIdx.x * blockDim.x + threadIdx.x;
    if (e < E) {
        int c = edge_at(ei, (long long)E + e, g_is64);   // col = dst
        if ((unsigned)c < (unsigned)n) atomicAdd(&g_cnt[c], 1);
    }
}

// Per-block exclusive scan of counts (1024/block) + dinv fused in.
__global__ void k_scan1(int n) {
    __shared__ int s[1024];
    int tid = threadIdx.x;
    int i = blockIdx.x * 1024 + tid;
    int v = (i < n) ? g_cnt[i] : 0;
    s[tid] = v; __syncthreads();
    #pragma unroll
    for (int d = 1; d < 1024; d <<= 1) {
        int t = (tid >= d) ? s[tid - d] : 0;
        __syncthreads();
        s[tid] += t;
        __syncthreads();
    }
    if (i < n) {
        g_off[i] = s[tid] - v;                 // block-local exclusive
        g_dinv[i] = rsqrtf((float)(v + 1));    // +1 = self loop
    }
    if (tid == 1023) g_bsum[blockIdx.x] = s[1023];
}

__global__ void k_scan2(int nb) {   // single block, nb <= 128
    __shared__ int s[128];
    int tid = threadIdx.x;
    int v = (tid < nb) ? g_bsum[tid] : 0;
    s[tid] = v; __syncthreads();
    #pragma unroll
    for (int d = 1; d < 128; d <<= 1) {
        int t = (tid >= d) ? s[tid - d] : 0;
        __syncthreads();
        s[tid] += t;
        __syncthreads();
    }
    if (tid < nb) g_bsum[tid] = s[tid] - v;    // exclusive block offsets
}

__global__ void k_fill(const void* __restrict__ ei, int E, int n) {
    int e = blockIdx.x * blockDim.x + threadIdx.x;
    if (e < E) {
        int is64 = g_is64;
        int r = edge_at(ei, e, is64);                    // row = src
        int c = edge_at(ei, (long long)E + e, is64);     // col = dst
        if ((unsigned)c < (unsigned)n && (unsigned)r < (unsigned)n) {
            int p = g_off[c] + g_bsum[c >> 10] + atomicAdd(&g_cur[c], 1);
            g_src[p] = r;
        }
    }
}

// ---------------- GEMM 1 (tensor): g1 = fp16( (x @ W1) * dinv[row] ) ----------
// 256 threads = 8 warps; each warp computes a 16-row x 64-col tile via
// mma.sync.m16n8k16.f32.f16.f16.f32 (8 k-steps x 8 n-chunks).
// W1 packed in smem as half2 over (k,k+1) pairs, row stride 72 half2 so that
// B-fragment LDS banks = (8t+g) mod 32 -> all 32 lanes distinct, conflict-free.
// A fragments: fp32 x loaded directly (LDG.64 per pair), converted to half2.
__global__ __launch_bounds__(256) void k_gemm1(const float* __restrict__ x,
                                               const float* __restrict__ W, int n) {
    __shared__ __half2 Wp[64 * 72];      // 18.4KB
    int tid = threadIdx.x;

    for (int i = tid; i < 64 * 64; i += 256) {
        int kp = i >> 6, nn = i & 63;
        Wp[kp * 72 + nn] = __floats2half2_rn(W[(2 * kp) * FHID + nn],
                                             W[(2 * kp + 1) * FHID + nn]);
    }
    __syncthreads();

    int warp = tid >> 5, lane = tid & 31;
    int g = lane >> 2, t = lane & 3;
    int row0 = blockIdx.x * G1_ROWS + warp * 16;
    int ra = min(row0 + g, n - 1);
    int rb = min(row0 + g + 8, n - 1);
    const float* xa = x + (size_t)ra * FIN;
    const float* xb = x + (size_t)rb * FIN;

    float d[8][4] = {};
    #pragma unroll
    for (int ks = 0; ks < 8; ks++) {
        int k0 = ks * 16;
        float2 va0 = __ldg((const float2*)(xa + k0 + 2 * t));
        float2 vb0 = __ldg((const float2*)(xb + k0 + 2 * t));
        float2 va1 = __ldg((const float2*)(xa + k0 + 8 + 2 * t));
        float2 vb1 = __ldg((const float2*)(xb + k0 + 8 + 2 * t));
        unsigned a0 = h2u(__floats2half2_rn(va0.x, va0.y));  // A[g][k0+2t..]
        unsigned a1 = h2u(__floats2half2_rn(vb0.x, vb0.y));  // A[g+8][k0+2t..]
        unsigned a2 = h2u(__floats2half2_rn(va1.x, va1.y));  // A[g][k0+8+2t..]
        unsigned a3 = h2u(__floats2half2_rn(vb1.x, vb1.y));  // A[g+8][k0+8+2t..]
        const __half2* wr0 = Wp + (ks * 8 + t) * 72;         // k rows 2t,2t+1
        const __half2* wr1 = wr0 + 4 * 72;                   // k rows 2t+8,2t+9
        #pragma unroll
        for (int nc = 0; nc < 8; nc++) {
            unsigned b0 = h2u(wr0[nc * 8 + g]);
            unsigned b1 = h2u(wr1[nc * 8 + g]);
            asm volatile(
                "mma.sync.aligned.m16n8k16.row.col.f32.f16.f16.f32 "
                "{%0,%1,%2,%3},{%4,%5,%6,%7},{%8,%9},{%0,%1,%2,%3};"
                : "+f"(d[nc][0]), "+f"(d[nc][1]), "+f"(d[nc][2]), "+f"(d[nc][3])
                : "r"(a0), "r"(a1), "r"(a2), "r"(a3), "r"(b0), "r"(b1));
        }
    }

    int r_lo = row0 + g, r_hi = row0 + g + 8;
    if (r_lo < n) {
        float dv = g_dinv[r_lo];
        __half* gp = g_g1h + (size_t)r_lo * FHID + 2 * t;
        #pragma unroll
        for (int nc = 0; nc < 8; nc++)
            *(__half2*)(gp + nc * 8) = __floats2half2_rn(d[nc][0] * dv, d[nc][1] * dv);
    }
    if (r_hi < n) {
        float dv = g_dinv[r_hi];
        __half* gp = g_g1h + (size_t)r_hi * FHID + 2 * t;
        #pragma unroll
        for (int nc = 0; nc < 8; nc++)
            *(__half2*)(gp + nc * 8) = __floats2half2_rn(d[nc][2] * dv, d[nc][3] * dv);
    }
}

// ---------------- GEMM 2: g2 = fp16( (hact @ W2) * dinv[row] ) ----------------
// 256 threads = 4 colgroups x 64 rowgroups; thread: 4 rows x 8 cols.
__global__ __launch_bounds__(256) void k_gemm2(const float* __restrict__ W, int n) {
    __shared__ float Ws[FHID * FOUT];    // 8KB
    int tid = threadIdx.x;
    int row0 = blockIdx.x * G2_ROWS;

    for (int i = tid; i < FHID * FOUT / 4; i += 256)
        ((float4*)Ws)[i] = ((const float4*)W)[i];
    __syncthreads();

    int cg = tid & 3;
    int rg = tid >> 2;
    int r0 = row0 + rg, r1 = r0 + 64, r2 = r0 + 128, r3 = r0 + 192;
    const float* xr0 = g_hact + (size_t)min(r0, n - 1) * FHID;
    const float* xr1 = g_hact + (size_t)min(r1, n - 1) * FHID;
    const float* xr2 = g_hact + (size_t)min(r2, n - 1) * FHID;
    const float* xr3 = g_hact + (size_t)min(r3, n - 1) * FHID;
    const float* w0 = Ws + cg * 4;
    const float* w1 = Ws + 16 + cg * 4;
    unsigned long long acc[4][4] = {};

    #pragma unroll 4
    for (int k = 0; k < FHID; k += 4) {
        float4 xv0 = __ldg((const float4*)(xr0 + k));
        float4 xv1 = __ldg((const float4*)(xr1 + k));
        float4 xv2 = __ldg((const float4*)(xr2 + k));
        float4 xv3 = __ldg((const float4*)(xr3 + k));
        #pragma unroll
        for (int s = 0; s < 4; s++) {
            ulonglong2 wA = *(const ulonglong2*)(w0 + (k + s) * FOUT);
            ulonglong2 wB = *(const ulonglong2*)(w1 + (k + s) * FOUT);
            unsigned long long d0 = pack_dup(((const float*)&xv0)[s]);
            unsigned long long d1 = pack_dup(((const float*)&xv1)[s]);
            unsigned long long d2 = pack_dup(((const float*)&xv2)[s]);
            unsigned long long d3 = pack_dup(((const float*)&xv3)[s]);
            FMA2(acc[0][0], d0, wA.x); FMA2(acc[0][1], d0, wA.y);
            FMA2(acc[0][2], d0, wB.x); FMA2(acc[0][3], d0, wB.y);
            FMA2(acc[1][0], d1, wA.x); FMA2(acc[1][1], d1, wA.y);
            FMA2(acc[1][2], d1, wB.x); FMA2(acc[1][3], d1, wB.y);
            FMA2(acc[2][0], d2, wA.x); FMA2(acc[2][1], d2, wA.y);
            FMA2(acc[2][2], d2, wB.x); FMA2(acc[2][3], d2, wB.y);
            FMA2(acc[3][0], d3, wA.x); FMA2(acc[3][1], d3, wA.y);
            FMA2(acc[3][2], d3, wB.x); FMA2(acc[3][3], d3, wB.y);
        }
    }
    #pragma unroll
    for (int i = 0; i < 4; i++) {
        int gr = row0 + rg + 64 * i;
        if (gr < n) {
            float dv = g_dinv[gr];
            float o[8];
            asm("mov.b64 {%0,%1},%2;" : "=f"(o[0]), "=f"(o[1]) : "l"(acc[i][0]));
            asm("mov.b64 {%0,%1},%2;" : "=f"(o[2]), "=f"(o[3]) : "l"(acc[i][1]));
            asm("mov.b64 {%0,%1},%2;" : "=f"(o[4]), "=f"(o[5]) : "l"(acc[i][2]));
            asm("mov.b64 {%0,%1},%2;" : "=f"(o[6]), "=f"(o[7]) : "l"(acc[i][3]));
            __half2 h0 = __floats2half2_rn(o[0] * dv, o[1] * dv);
            __half2 h1 = __floats2half2_rn(o[2] * dv, o[3] * dv);
            __half2 h2 = __floats2half2_rn(o[4] * dv, o[5] * dv);
            __half2 h3 = __floats2half2_rn(o[6] * dv, o[7] * dv);
            __half* gp = g_g2h + (size_t)gr * FOUT;
            *(uint2*)(gp + cg * 4)      = make_uint2(h2u(h0), h2u(h1));
            *(uint2*)(gp + 16 + cg * 4) = make_uint2(h2u(h2), h2u(h3));
        }
    }
}

// ---------------- Gather aggregation: one warp per node, MLP=4, fp16 operands ---
// h_act[v] = relu( dinv[v] * (sum_{u->v} g1[u] + g1[v]) + b1 )
__global__ void k_gather1(const float* __restrict__ bias, int n) {
    int t = blockIdx.x * blockDim.x + threadIdx.x;
    int v = t >> 5;
    int lane = t & 31;
    if (v >= n) return;
    int base = g_off[v] + g_bsum[v >> 10];
    int c = g_cnt[v];
    const __half2* g1 = (const __half2*)g_g1h;   // row stride = 32 half2

    float2 acc = __half22float2(__ldg(g1 + (size_t)v * 32 + lane));  // self loop
    int j = 0;
    for (; j + 4 <= c; j += 4) {
        int u0 = __ldg(&g_src[base + j + 0]);
        int u1 = __ldg(&g_src[base + j + 1]);
        int u2 = __ldg(&g_src[base + j + 2]);
        int u3 = __ldg(&g_src[base + j + 3]);
        float2 t0 = __half22float2(__ldg(g1 + (size_t)u0 * 32 + lane));
        float2 t1 = __half22float2(__ldg(g1 + (size_t)u1 * 32 + lane));
        float2 t2 = __half22float2(__ldg(g1 + (size_t)u2 * 32 + lane));
        float2 t3 = __half22float2(__ldg(g1 + (size_t)u3 * 32 + lane));
        acc.x += t0.x + t1.x + t2.x + t3.x;
        acc.y += t0.y + t1.y + t2.y + t3.y;
    }
    for (; j < c; j++) {
        int u = __ldg(&g_src[base + j]);
        float2 tt = __half22float2(__ldg(g1 + (size_t)u * 32 + lane));
        acc.x += tt.x; acc.y += tt.y;
    }
    float dv = g_dinv[v];
    float o0 = fmaf(dv, acc.x, bias[lane * 2]);
    float o1 = fmaf(dv, acc.y, bias[lane * 2 + 1]);
    o0 = fmaxf(o0, 0.f); o1 = fmaxf(o1, 0.f);
    *(float2*)(g_hact + (size_t)v * FHID + lane * 2) = make_float2(o0, o1);
}

// out[v] = dinv[v] * (sum_{u->v} g2[u] + g2[v]) + b2
__global__ void k_gather2(const float* __restrict__ bias, float* __restrict__ outp, int n) {
    int t = blockIdx.x * blockDim.x + threadIdx.x;
    int v = t >> 5;
    int lane = t & 31;
    if (v >= n) return;
    int base = g_off[v] + g_bsum[v >> 10];
    int c = g_cnt[v];

    float acc = __half2float(__ldg(g_g2h + (size_t)v * FOUT + lane));  // self loop
    int j = 0;
    for (; j + 4 <= c; j += 4) {
        int u0 = __ldg(&g_src[base + j + 0]);
        int u1 = __ldg(&g_src[base + j + 1]);
        int u2 = __ldg(&g_src[base + j + 2]);
        int u3 = __ldg(&g_src[base + j + 3]);
        float t0 = __half2float(__ldg(g_g2h + (size_t)u0 * FOUT + lane));
        float t1 = __half2float(__ldg(g_g2h + (size_t)u1 * FOUT + lane));
        float t2 = __half2float(__ldg(g_g2h + (size_t)u2 * FOUT + lane));
        float t3 = __half2float(__ldg(g_g2h + (size_t)u3 * FOUT + lane));
        acc += t0 + t1 + t2 + t3;
    }
    for (; j < c; j++) {
        int u = __ldg(&g_src[base + j]);
        acc += __half2float(__ldg(g_g2h + (size_t)u * FOUT + lane));
    }
    float dv = g_dinv[v];
    outp[(size_t)v * FOUT + lane] = fmaf(dv, acc, bias[lane]);
}

// ---------------- launch ----------------
extern "C" void kernel_launch(void* const* d_in, const int* in_sizes, int n_in,
                              void* d_out, int out_size) {
    const float* x   = (const float*)d_in[0];
    const void*  ei  = d_in[1];                 // int32 or int64, detected on device
    const float* W1  = (const float*)d_in[2];
    const float* b1  = (const float*)d_in[3];
    const float* W2  = (const float*)d_in[4];
    const float* b2  = (const float*)d_in[5];
    float*       out = (float*)d_out;

    int n = in_sizes[0] / FIN;     // 100000
    int E = in_sizes[1] / 2;       // 1600000 (element count is dtype-independent)

    int nb = (n + 1023) / 1024;

    k_init <<<(n + 255) / 256, 256>>>((const int*)ei, n);
    k_count<<<(E + 255) / 256, 256>>>(ei, E, n);
    k_scan1<<<nb, 1024>>>(n);                                   // off + dinv + bsum
    k_gemm1<<<(n + G1_ROWS - 1) / G1_ROWS, 256>>>(x, W1, n);    // 4th launch: ncu window
    k_scan2<<<1, 128>>>(nb);
    k_fill <<<(E + 255) / 256, 256>>>(ei, E, n);
    k_gather1<<<(int)(((size_t)n * 32 + 255) / 256), 256>>>(b1, n);
    k_gemm2<<<(n + G2_ROWS - 1) / G2_ROWS, 256>>>(W2, n);
    k_gather2<<<(int)(((size_t)n * 32 + 255) / 256), 256>>>(b2, out, n);
}

// round 16
// speedup vs baseline: 1.5223x; 1.1071x over previous
#include <cuda_runtime.h>
#include <cuda_bf16.h>
#include <cuda_fp16.h>
#include <cstdint>

// Problem constants (shapes fixed by the dataset)
#define MAXN 100000
#define MAXE 1600000
#define FIN  128
#define FHID 64
#define FOUT 32

// GEMM tiling (rows per CTA)
#define G1_ROWS 128            // 8 warps x 16 rows (mma m16n8k16)
#define G2_ROWS 128            // 8 warps x 16 rows

// ---------------- device scratch (no allocations allowed) ----------------
__device__ int    g_is64;          // 1 if edge_index is int64, 0 if int32
__device__ int    g_cnt[MAXN];     // in-degree (real edges only)
__device__ int    g_cur[MAXN];     // fill cursors
__device__ int    g_off[MAXN];     // CSR offsets (block-local exclusive scan)
__device__ int    g_bsum[128];     // per-block scan offsets (exclusive)
__device__ float  g_dinv[MAXN];    // deg^{-1/2} (deg includes self loop)
__device__ int    g_src[MAXE];     // CSR: source node per (dst-sorted) edge
__device__ __half g_g1h[(size_t)MAXN * FHID];  // (x@W1)*dinv, fp16
__device__ __half g_hacth[(size_t)MAXN * FHID];// relu layer-1 output, fp16
__device__ __half g_g2h[(size_t)MAXN * FOUT];  // (hact@W2)*dinv, fp16

// ---------------- small helpers ----------------
__device__ __forceinline__ unsigned h2u(__half2 h) {
    unsigned u; __builtin_memcpy(&u, &h, 4); return u;
}

__device__ __forceinline__ int edge_at(const void* ei, long long idx, int is64) {
    if (is64) return (int)((const long long*)ei)[idx];
    return ((const int*)ei)[idx];
}

#define MMA16816(D, A0, A1, A2, A3, B0, B1)                                     \
    asm volatile(                                                               \
        "mma.sync.aligned.m16n8k16.row.col.f32.f16.f16.f32 "                    \
        "{%0,%1,%2,%3},{%4,%5,%6,%7},{%8,%9},{%0,%1,%2,%3};"                    \
        : "+f"(D[0]), "+f"(D[1]), "+f"(D[2]), "+f"(D[3])                        \
        : "r"(A0), "r"(A1), "r"(A2), "r"(A3), "r"(B0), "r"(B1))

// ---------------- init: zero counters + detect edge dtype ----------------
// int64 little-endian values < 2^31  => every odd 32-bit word is zero.
__global__ void k_init(const int* ei32, int n) {
    int i = blockIdx.x * blockDim.x + threadIdx.x;
    if (i < n) { g_cnt[i] = 0; g_cur[i] = 0; }
    if (blockIdx.x == 0 && threadIdx.x < 32) {
        int lane = threadIdx.x;
        int nz = 0;
        #pragma unroll
        for (int q = 0; q < 8; q++) nz |= ei32[2 * (lane * 8 + q) + 1];
        unsigned m = __ballot_sync(0xffffffffu, nz != 0);
        if (lane == 0) g_is64 = (m == 0) ? 1 : 0;
    }
}

__global__ void k_count(const void* __restrict__ ei, int E, int n) {
    int e = blockIdx.x * blockDim.x + threadIdx.x;
    if (e < E) {
        int c = edge_at(ei, (long long)E + e, g_is64);   // col = dst
        if ((unsigned)c < (unsigned)n) atomicAdd(&g_cnt[c], 1);
    }
}

// Per-block exclusive scan of counts (1024/block) + dinv fused in.
__global__ void k_scan1(int n) {
    __shared__ int s[1024];
    int tid = threadIdx.x;
    int i = blockIdx.x * 1024 + tid;
    int v = (i < n) ? g_cnt[i] : 0;
    s[tid] = v; __syncthreads();
    #pragma unroll
    for (int d = 1; d < 1024; d <<= 1) {
        int t = (tid >= d) ? s[tid - d] : 0;
        __syncthreads();
        s[tid] += t;
        __syncthreads();
    }
    if (i < n) {
        g_off[i] = s[tid] - v;                 // block-local exclusive
        g_dinv[i] = rsqrtf((float)(v + 1));    // +1 = self loop
    }
    if (tid == 1023) g_bsum[blockIdx.x] = s[1023];
}

__global__ void k_scan2(int nb) {   // single block, nb <= 128
    __shared__ int s[128];
    int tid = threadIdx.x;
    int v = (tid < nb) ? g_bsum[tid] : 0;
    s[tid] = v; __syncthreads();
    #pragma unroll
    for (int d = 1; d < 128; d <<= 1) {
        int t = (tid >= d) ? s[tid - d] : 0;
        __syncthreads();
        s[tid] += t;
        __syncthreads();
    }
    if (tid < nb) g_bsum[tid] = s[tid] - v;    // exclusive block offsets
}

__global__ void k_fill(const void* __restrict__ ei, int E, int n) {
    int e = blockIdx.x * blockDim.x + threadIdx.x;
    if (e < E) {
        int is64 = g_is64;
        int r = edge_at(ei, e, is64);                    // row = src
        int c = edge_at(ei, (long long)E + e, is64);     // col = dst
        if ((unsigned)c < (unsigned)n && (unsigned)r < (unsigned)n) {
            int p = g_off[c] + g_bsum[c >> 10] + atomicAdd(&g_cur[c], 1);
            g_src[p] = r;
        }
    }
}

// ---------------- GEMM 1 (tensor): g1 = fp16( (x @ W1) * dinv[row] ) ----------
// 256 threads = 8 warps; each warp computes a 16-row x 64-col tile via
// mma.sync.m16n8k16 (8 k-steps x 8 n-chunks). W1 packed half2, row stride 72:
// B-fragment LDS banks = (8t+g) mod 32 -> conflict-free.
// x loads are software-pipelined: ks+1's 4 LDG.64 issue before ks's MMAs.
__global__ __launch_bounds__(256) void k_gemm1(const float* __restrict__ x,
                                               const float* __restrict__ W, int n) {
    __shared__ __half2 Wp[64 * 72];      // 18.4KB
    int tid = threadIdx.x;

    for (int i = tid; i < 64 * 64; i += 256) {
        int kp = i >> 6, nn = i & 63;
        Wp[kp * 72 + nn] = __floats2half2_rn(W[(2 * kp) * FHID + nn],
                                             W[(2 * kp + 1) * FHID + nn]);
    }
    __syncthreads();

    int warp = tid >> 5, lane = tid & 31;
    int g = lane >> 2, t = lane & 3;
    int row0 = blockIdx.x * G1_ROWS + warp * 16;
    int ra = min(row0 + g, n - 1);
    int rb = min(row0 + g + 8, n - 1);
    const float* xa = x + (size_t)ra * FIN;
    const float* xb = x + (size_t)rb * FIN;

    float d[8][4] = {};
    float2 pa0 = __ldg((const float2*)(xa + 2 * t));
    float2 pb0 = __ldg((const float2*)(xb + 2 * t));
    float2 pa1 = __ldg((const float2*)(xa + 8 + 2 * t));
    float2 pb1 = __ldg((const float2*)(xb + 8 + 2 * t));
    #pragma unroll
    for (int ks = 0; ks < 8; ks++) {
        float2 ca0 = pa0, cb0 = pb0, ca1 = pa1, cb1 = pb1;
        if (ks < 7) {
            int k1 = (ks + 1) * 16;
            pa0 = __ldg((const float2*)(xa + k1 + 2 * t));
            pb0 = __ldg((const float2*)(xb + k1 + 2 * t));
            pa1 = __ldg((const float2*)(xa + k1 + 8 + 2 * t));
            pb1 = __ldg((const float2*)(xb + k1 + 8 + 2 * t));
        }
        unsigned a0 = h2u(__floats2half2_rn(ca0.x, ca0.y));
        unsigned a1 = h2u(__floats2half2_rn(cb0.x, cb0.y));
        unsigned a2 = h2u(__floats2half2_rn(ca1.x, ca1.y));
        unsigned a3 = h2u(__floats2half2_rn(cb1.x, cb1.y));
        const __half2* wr0 = Wp + (ks * 8 + t) * 72;
        const __half2* wr1 = wr0 + 4 * 72;
        #pragma unroll
        for (int nc = 0; nc < 8; nc++) {
            unsigned b0 = h2u(wr0[nc * 8 + g]);
            unsigned b1 = h2u(wr1[nc * 8 + g]);
            MMA16816(d[nc], a0, a1, a2, a3, b0, b1);
        }
    }

    int r_lo = row0 + g, r_hi = row0 + g + 8;
    if (r_lo < n) {
        float dv = g_dinv[r_lo];
        __half* gp = g_g1h + (size_t)r_lo * FHID + 2 * t;
        #pragma unroll
        for (int nc = 0; nc < 8; nc++)
            *(__half2*)(gp + nc * 8) = __floats2half2_rn(d[nc][0] * dv, d[nc][1] * dv);
    }
    if (r_hi < n) {
        float dv = g_dinv[r_hi];
        __half* gp = g_g1h + (size_t)r_hi * FHID + 2 * t;
        #pragma unroll
        for (int nc = 0; nc < 8; nc++)
            *(__half2*)(gp + nc * 8) = __floats2half2_rn(d[nc][2] * dv, d[nc][3] * dv);
    }
}

// ---------------- GEMM 2 (tensor): g2 = fp16( (hact @ W2) * dinv[row] ) -------
// 8 warps x 16 rows; N=32 (4 n-chunks), K=64 (4 k-steps). A is fp16 in
// g_hacth -> direct half2 loads, fully unrolled (16 independent LDG.32).
// W2 packed half2, stride 40: banks (8t+g) mod 32 -> conflict-free.
__global__ __launch_bounds__(256) void k_gemm2(const float* __restrict__ W, int n) {
    __shared__ __half2 Wp[32 * 40];      // 5.1KB
    int tid = threadIdx.x;

    for (int i = tid; i < 32 * 32; i += 256) {
        int kp = i >> 5, nn = i & 31;
        Wp[kp * 40 + nn] = __floats2half2_rn(W[(2 * kp) * FOUT + nn],
                                             W[(2 * kp + 1) * FOUT + nn]);
    }
    __syncthreads();

    int warp = tid >> 5, lane = tid & 31;
    int g = lane >> 2, t = lane & 3;
    int row0 = blockIdx.x * G2_ROWS + warp * 16;
    int ra = min(row0 + g, n - 1);
    int rb = min(row0 + g + 8, n - 1);
    const __half* xa = g_hacth + (size_t)ra * FHID;
    const __half* xb = g_hacth + (size_t)rb * FHID;

    float d[4][4] = {};
    #pragma unroll
    for (int ks = 0; ks < 4; ks++) {
        int k0 = ks * 16;
        unsigned a0 = __ldg((const unsigned*)(xa + k0 + 2 * t));
        unsigned a1 = __ldg((const unsigned*)(xb + k0 + 2 * t));
        unsigned a2 = __ldg((const unsigned*)(xa + k0 + 8 + 2 * t));
        unsigned a3 = __ldg((const unsigned*)(xb + k0 + 8 + 2 * t));
        const __half2* wr0 = Wp + (ks * 8 + t) * 40;
        const __half2* wr1 = wr0 + 4 * 40;
        #pragma unroll
        for (int nc = 0; nc < 4; nc++) {
            unsigned b0 = h2u(wr0[nc * 8 + g]);
            unsigned b1 = h2u(wr1[nc * 8 + g]);
            MMA16816(d[nc], a0, a1, a2, a3, b0, b1);
        }
    }

    int r_lo = row0 + g, r_hi = row0 + g + 8;
    if (r_lo < n) {
        float dv = g_dinv[r_lo];
        __half* gp = g_g2h + (size_t)r_lo * FOUT + 2 * t;
        #pragma unroll
        for (int nc = 0; nc < 4; nc++)
            *(__half2*)(gp + nc * 8) = __floats2half2_rn(d[nc][0] * dv, d[nc][1] * dv);
    }
    if (r_hi < n) {
        float dv = g_dinv[r_hi];
        __half* gp = g_g2h + (size_t)r_hi * FOUT + 2 * t;
        #pragma unroll
        for (int nc = 0; nc < 4; nc++)
            *(__half2*)(gp + nc * 8) = __floats2half2_rn(d[nc][2] * dv, d[nc][3] * dv);
    }
}

// ---------------- Gather aggregation: one warp per node, MLP=4, fp16 operands ---
// hact[v] = fp16( relu( dinv[v] * (sum_{u->v} g1[u] + g1[v]) + b1 ) )
__global__ void k_gather1(const float* __restrict__ bias, int n) {
    int t = blockIdx.x * blockDim.x + threadIdx.x;
    int v = t >> 5;
    int lane = t & 31;
    if (v >= n) return;
    int base = g_off[v] + g_bsum[v >> 10];
    int c = g_cnt[v];
    const __half2* g1 = (const __half2*)g_g1h;   // row stride = 32 half2

    float2 acc = __half22float2(__ldg(g1 + (size_t)v * 32 + lane));  // self loop
    int j = 0;
    for (; j + 4 <= c; j += 4) {
        int u0 = __ldg(&g_src[base + j + 0]);
        int u1 = __ldg(&g_src[base + j + 1]);
        int u2 = __ldg(&g_src[base + j + 2]);
        int u3 = __ldg(&g_src[base + j + 3]);
        float2 t0 = __half22float2(__ldg(g1 + (size_t)u0 * 32 + lane));
        float2 t1 = __half22float2(__ldg(g1 + (size_t)u1 * 32 + lane));
        float2 t2 = __half22float2(__ldg(g1 + (size_t)u2 * 32 + lane));
        float2 t3 = __half22float2(__ldg(g1 + (size_t)u3 * 32 + lane));
        acc.x += t0.x + t1.x + t2.x + t3.x;
        acc.y += t0.y + t1.y + t2.y + t3.y;
    }
    for (; j < c; j++) {
        int u = __ldg(&g_src[base + j]);
        float2 tt = __half22float2(__ldg(g1 + (size_t)u * 32 + lane));
        acc.x += tt.x; acc.y += tt.y;
    }
    float dv = g_dinv[v];
    float o0 = fmaf(dv, acc.x, bias[lane * 2]);
    float o1 = fmaf(dv, acc.y, bias[lane * 2 + 1]);
    o0 = fmaxf(o0, 0.f); o1 = fmaxf(o1, 0.f);
    *(__half2*)(g_hacth + (size_t)v * FHID + lane * 2) = __floats2half2_rn(o0, o1);
}

// out[v] = dinv[v] * (sum_{u->v} g2[u] + g2[v]) + b2
__global__ void k_gather2(const float* __restrict__ bias, float* __restrict__ outp, int n) {
    int t = blockIdx.x * blockDim.x + threadIdx.x;
    int v = t >> 5;
    int lane = t & 31;
    if (v >= n) return;
    int base = g_off[v] + g_bsum[v >> 10];
    int c = g_cnt[v];

    float acc = __half2float(__ldg(g_g2h + (size_t)v * FOUT + lane));  // self loop
    int j = 0;
    for (; j + 4 <= c; j += 4) {
        int u0 = __ldg(&g_src[base + j + 0]);
        int u1 = __ldg(&g_src[base + j + 1]);
        int u2 = __ldg(&g_src[base + j + 2]);
        int u3 = __ldg(&g_src[base + j + 3]);
        float t0 = __half2float(__ldg(g_g2h + (size_t)u0 * FOUT + lane));
        float t1 = __half2float(__ldg(g_g2h + (size_t)u1 * FOUT + lane));
        float t2 = __half2float(__ldg(g_g2h + (size_t)u2 * FOUT + lane));
        float t3 = __half2float(__ldg(g_g2h + (size_t)u3 * FOUT + lane));
        acc += t0 + t1 + t2 + t3;
    }
    for (; j < c; j++) {
        int u = __ldg(&g_src[base + j]);
        acc += __half2float(__ldg(g_g2h + (size_t)u * FOUT + lane));
    }
    float dv = g_dinv[v];
    outp[(size_t)v * FOUT + lane] = fmaf(dv, acc, bias[lane]);
}

// ---------------- launch ----------------
extern "C" void kernel_launch(void* const* d_in, const int* in_sizes, int n_in,
                              void* d_out, int out_size) {
    const float* x   = (const float*)d_in[0];
    const void*  ei  = d_in[1];                 // int32 or int64, detected on device
    const float* W1  = (const float*)d_in[2];
    const float* b1  = (const float*)d_in[3];
    const float* W2  = (const float*)d_in[4];
    const float* b2  = (const float*)d_in[5];
    float*       out = (float*)d_out;

    int n = in_sizes[0] / FIN;     // 100000
    int E = in_sizes[1] / 2;       // 1600000 (element count is dtype-independent)

    int nb = (n + 1023) / 1024;

    k_init <<<(n + 255) / 256, 256>>>((const int*)ei, n);
    k_count<<<(E + 255) / 256, 256>>>(ei, E, n);
    k_scan1<<<nb, 1024>>>(n);                                   // off + dinv + bsum
    k_gemm1<<<(n + G1_ROWS - 1) / G1_ROWS, 256>>>(x, W1, n);    // 4th launch: ncu window
    k_scan2<<<1, 128>>>(nb);
    k_fill <<<(E + 255) / 256, 256>>>(ei, E, n);
    k_gather1<<<(int)(((size_t)n * 32 + 255) / 256), 256>>>(b1, n);
    k_gemm2<<<(n + G2_ROWS - 1) / G2_ROWS, 256>>>(W2, n);
    k_gather2<<<(int)(((size_t)n * 32 + 255) / 256), 256>>>(b2, out, n);
}